// round 1
// baseline (speedup 1.0000x reference)
#include <cuda_runtime.h>
#include <math.h>

#define BB 32
#define NPB 2048
#define NN 65536
#define EE 1048576
#define HH 768
#define NH 8
#define DHH 96
#define SCALE_V 0.10206207261596577f

// ---------------- scratch (device globals; no allocation) ----------------
__device__ float g_qp[BB*HH], g_q[BB*HH], g_qp2[BB*HH], g_T[BB*HH];
__device__ float g_U[BB*NH*HH];
__device__ float g_c[BB], g_qn[BB];
__device__ float g_scores[(size_t)NN*NH];
__device__ float g_num[NN], g_nsq[NN];
__device__ float g_mx[BB*NH], g_se[BB*NH];
__device__ float g_wsum[BB*NH*HH];
__device__ float g_meanx[BB*HH];
__device__ float g_ctx[BB*HH], g_tmp1[BB*HH], g_graph[BB*HH];
__device__ int   g_first_edge[NN];
__device__ float g_meanpaths[BB*HH];
__device__ int   g_cnt[BB];
__device__ float g_bmean[BB*HH], g_agg1[BB*HH], g_agg[BB*HH], g_pathpre[BB*HH], g_path[BB*HH];
__device__ float g_comb[BB*3*HH], g_gate[BB*HH], g_fused[BB*HH];

// ---------------- init ----------------
__global__ void k_init() {
    int i = blockIdx.x * blockDim.x + threadIdx.x;
    if (i < NN) { g_first_edge[i] = EE; g_nsq[i] = 0.f; }
}

// ---------------- generic small GEMM: C[32,N] = act(A[32,K] @ B(+T) + bias) ----------------
// act: 0 none, 1 relu, 2 sigmoid. transB: B stored [N,K] row-major.
__global__ void k_gemm(const float* __restrict__ A, int lda,
                       const float* __restrict__ Bm, int ldb, int transB,
                       const float* __restrict__ bias,
                       float* __restrict__ C, int ldc,
                       int M, int Ncols, int K, int act)
{
    __shared__ float sA[32][33];
    __shared__ float sB[32][132];
    int t = threadIdx.x;            // 256
    int c0 = blockIdx.x * 128;
    int jj = t & 127;
    int rg = t >> 7;                // 0..1 -> rows rg*16..rg*16+15
    float acc[16];
#pragma unroll
    for (int r = 0; r < 16; r++) acc[r] = 0.f;

    for (int k0 = 0; k0 < K; k0 += 32) {
        for (int idx = t; idx < 32*32; idx += 256) {
            int m = idx >> 5, kk = idx & 31;
            sA[m][kk] = (m < M) ? A[(size_t)m*lda + k0 + kk] : 0.f;
        }
        if (!transB) {
            for (int idx = t; idx < 32*128; idx += 256) {
                int kk = idx >> 7, nn = idx & 127;
                int col = c0 + nn;
                sB[kk][nn] = (col < Ncols) ? Bm[(size_t)(k0+kk)*ldb + col] : 0.f;
            }
        } else {
            for (int idx = t; idx < 32*128; idx += 256) {
                int nn = idx >> 5, kk = idx & 31;
                int col = c0 + nn;
                sB[kk][nn] = (col < Ncols) ? Bm[(size_t)col*ldb + k0 + kk] : 0.f;
            }
        }
        __syncthreads();
#pragma unroll 8
        for (int kk = 0; kk < 32; kk++) {
            float bv = sB[kk][jj];
#pragma unroll
            for (int r = 0; r < 16; r++)
                acc[r] += sA[rg*16 + r][kk] * bv;
        }
        __syncthreads();
    }
    int col = c0 + jj;
    if (col < Ncols) {
        float bb = bias ? bias[col] : 0.f;
#pragma unroll
        for (int r = 0; r < 16; r++) {
            int m = rg*16 + r;
            if (m < M) {
                float v = acc[r] + bb;
                if (act == 1) v = fmaxf(v, 0.f);
                else if (act == 2) v = 1.f / (1.f + expf(-v));
                C[(size_t)m*ldc + col] = v;
            }
        }
    }
}

// ---------------- qp2 stats: qn[b] = max(||qp2||,1e-8), c[b] = qp2 . pf_bn ----------------
__global__ void k_qstats(const float* __restrict__ bn) {
    int b = blockIdx.x, t = threadIdx.x;
    __shared__ float s1[256], s2[256];
    float a = 0.f, d = 0.f;
    for (int j = t; j < HH; j += 256) {
        float v = g_qp2[b*HH + j];
        a += v * v; d += v * bn[j];
    }
    s1[t] = a; s2[t] = d; __syncthreads();
    for (int o = 128; o > 0; o >>= 1) {
        if (t < o) { s1[t] += s1[t+o]; s2[t] += s2[t+o]; }
        __syncthreads();
    }
    if (t == 0) { g_qn[b] = fmaxf(sqrtf(s1[0]), 1e-8f); g_c[b] = s2[0]; }
}

// ---------------- per-node scores (8 heads) + cosine numerator ----------------
__global__ void k_scores(const float* __restrict__ X) {
    __shared__ float sU[NH*HH];
    __shared__ float sT[HH];
    int b = blockIdx.x >> 3;           // 8 CTAs per batch
    int cta_in_b = blockIdx.x & 7;
    for (int i = threadIdx.x; i < NH*HH; i += 256) sU[i] = g_U[b*NH*HH + i];
    for (int i = threadIdx.x; i < HH;    i += 256) sT[i] = g_T[b*HH + i];
    __syncthreads();
    float cb = g_c[b];
    int warp = threadIdx.x >> 5, lane = threadIdx.x & 31;
    int nodebase = b*NPB + cta_in_b*256 + warp*32;
    for (int w = 0; w < 32; w++) {
        int n = nodebase + w;
        const float* xr = X + (size_t)n*HH;
        float acc[9];
#pragma unroll
        for (int i = 0; i < 9; i++) acc[i] = 0.f;
        for (int cc = 0; cc < HH/32; cc++) {
            int base = cc*32 + lane;
            float xv = xr[base];
#pragma unroll
            for (int h = 0; h < 8; h++) acc[h] += xv * sU[h*HH + base];
            acc[8] += xv * sT[base];
        }
#pragma unroll
        for (int i = 0; i < 9; i++)
            for (int o = 16; o > 0; o >>= 1)
                acc[i] += __shfl_xor_sync(0xffffffffu, acc[i], o);
        if (lane == 0) {
#pragma unroll
            for (int h = 0; h < 8; h++) g_scores[(size_t)n*NH + h] = acc[h] * SCALE_V;
            g_num[n] = acc[8] + cb;
        }
    }
}

// ---------------- big GEMM: row norms of (X @ Wn + bn) ----------------
__global__ void k_normgemm(const float* __restrict__ X, const float* __restrict__ W,
                           const float* __restrict__ bn)
{
    __shared__ float As[8][132];
    __shared__ float Bs[8][132];
    __shared__ float srow[128];
    int t = threadIdx.x;                 // 256
    int tx = t & 15, ty = t >> 4;        // 16x16
    int r0 = blockIdx.x * 128, c0 = blockIdx.y * 128;
    float acc[8][8];
#pragma unroll
    for (int r = 0; r < 8; r++)
#pragma unroll
        for (int c = 0; c < 8; c++) acc[r][c] = 0.f;

    for (int k0 = 0; k0 < HH; k0 += 8) {
        for (int idx = t; idx < 1024; idx += 256) {
            int m = idx >> 3, kk = idx & 7;
            As[kk][m] = X[(size_t)(r0 + m)*HH + k0 + kk];
        }
        for (int idx = t; idx < 1024; idx += 256) {
            int kk = idx >> 7, nn = idx & 127;
            Bs[kk][nn] = W[(size_t)(k0 + kk)*HH + c0 + nn];
        }
        __syncthreads();
#pragma unroll
        for (int kk = 0; kk < 8; kk++) {
            float ra[8], rb[8];
#pragma unroll
            for (int r = 0; r < 8; r++) ra[r] = As[kk][ty + 16*r];
#pragma unroll
            for (int c = 0; c < 8; c++) rb[c] = Bs[kk][tx + 16*c];
#pragma unroll
            for (int r = 0; r < 8; r++)
#pragma unroll
                for (int c = 0; c < 8; c++) acc[r][c] += ra[r] * rb[c];
        }
        __syncthreads();
    }
    if (t < 128) srow[t] = 0.f;
    __syncthreads();
#pragma unroll
    for (int r = 0; r < 8; r++) {
        float s = 0.f;
#pragma unroll
        for (int c = 0; c < 8; c++) {
            float v = acc[r][c] + bn[c0 + tx + 16*c];
            s += v * v;
        }
        atomicAdd(&srow[ty + 16*r], s);
    }
    __syncthreads();
    if (t < 128) atomicAdd(&g_nsq[r0 + t], srow[t]);
}

// ---------------- softmax stats per (b,h) ----------------
__global__ void k_smstats() {
    int b = blockIdx.x >> 3, h = blockIdx.x & 7;
    int t = threadIdx.x;
    __shared__ float sm[256];
    float m = -1e30f;
    for (int i = t; i < NPB; i += 256)
        m = fmaxf(m, g_scores[(size_t)(b*NPB + i)*NH + h]);
    sm[t] = m; __syncthreads();
    for (int o = 128; o > 0; o >>= 1) { if (t < o) sm[t] = fmaxf(sm[t], sm[t+o]); __syncthreads(); }
    float mx = sm[0]; __syncthreads();
    float s = 0.f;
    for (int i = t; i < NPB; i += 256)
        s += expf(g_scores[(size_t)(b*NPB + i)*NH + h] - mx);
    sm[t] = s; __syncthreads();
    for (int o = 128; o > 0; o >>= 1) { if (t < o) sm[t] += sm[t+o]; __syncthreads(); }
    if (t == 0) { g_mx[b*NH + h] = mx; g_se[b*NH + h] = sm[0]; }
}

// ---------------- attention-weighted raw-feature sums + per-batch mean(x) ----------------
__global__ void k_wsum(const float* __restrict__ X) {
    int b = blockIdx.x, ch = blockIdx.y;
    int t = threadIdx.x;                // 128
    __shared__ float sa[128][8];
    __shared__ float smx[8], sse[8];
    if (t < 8) { smx[t] = g_mx[b*NH + t]; sse[t] = 1.f / g_se[b*NH + t]; }
    __syncthreads();
    float acc[8];
#pragma unroll
    for (int h = 0; h < 8; h++) acc[h] = 0.f;
    float msum = 0.f;
    int col = ch*128 + t;
    for (int n0 = 0; n0 < NPB; n0 += 128) {
        size_t n = (size_t)(b*NPB + n0 + t);
#pragma unroll
        for (int h = 0; h < 8; h++)
            sa[t][h] = expf(g_scores[n*NH + h] - smx[h]) * sse[h];
        __syncthreads();
        for (int nn = 0; nn < 128; nn++) {
            float xv = X[(size_t)(b*NPB + n0 + nn)*HH + col];
            msum += xv;
#pragma unroll
            for (int h = 0; h < 8; h++) acc[h] += sa[nn][h] * xv;
        }
        __syncthreads();
    }
#pragma unroll
    for (int h = 0; h < 8; h++) g_wsum[(size_t)(b*NH + h)*HH + col] = acc[h];
    g_meanx[b*HH + col] = msum * (1.f / (float)NPB);
}

// ---------------- edges: first outgoing intra-graph edge per node ----------------
__global__ void k_edges(const int* __restrict__ ei, const int* __restrict__ bidx) {
    int e = blockIdx.x * blockDim.x + threadIdx.x;
    if (e < EE) {
        int s = ei[e], d = ei[EE + e];
        if (bidx[s] == bidx[d]) atomicMin(&g_first_edge[s], e);
    }
}

// ---------------- top-3 cosine starts + path features ----------------
__global__ void k_paths(const float* __restrict__ X, const int* __restrict__ ei) {
    int b = blockIdx.x, t = threadIdx.x;
    __shared__ float sv[768]; __shared__ int si[768];
    __shared__ int st[3], snb[3], sval[3], scnt;
    float qninv = 1.f / g_qn[b];
    float v0 = -1e38f, v1 = -1e38f, v2 = -1e38f;
    int i0 = 0x7fffffff, i1 = 0x7fffffff, i2 = 0x7fffffff;
    for (int i = t; i < NPB; i += 256) {
        int n = b*NPB + i;
        float nn_ = fmaxf(sqrtf(g_nsq[n]), 1e-8f);
        float sim = g_num[n] * qninv / nn_;
        if (sim > v0)      { v2=v1;i2=i1; v1=v0;i1=i0; v0=sim;i0=n; }
        else if (sim > v1) { v2=v1;i2=i1; v1=sim;i1=n; }
        else if (sim > v2) { v2=sim;i2=n; }
    }
    sv[t*3+0]=v0; si[t*3+0]=i0;
    sv[t*3+1]=v1; si[t*3+1]=i1;
    sv[t*3+2]=v2; si[t*3+2]=i2;
    __syncthreads();
    if (t == 0) {
        float b0=-1e38f,b1=-1e38f,b2=-1e38f;
        int j0=0x7fffffff,j1=0x7fffffff,j2=0x7fffffff;
        for (int i = 0; i < 768; i++) {
            float v = sv[i]; int ix = si[i];
            if ((v>b0) || (v==b0 && ix<j0))      { b2=b1;j2=j1; b1=b0;j1=j0; b0=v;j0=ix; }
            else if ((v>b1) || (v==b1 && ix<j1)) { b2=b1;j2=j1; b1=v;j1=ix; }
            else if ((v>b2) || (v==b2 && ix<j2)) { b2=v;j2=ix; }
        }
        int ss[3] = { j0, j1, j2 };
        int c = 0;
        for (int k = 0; k < 3; k++) {
            int fe = g_first_edge[ss[k]];
            int vl = (fe < EE) ? 1 : 0;
            int nbr = ei[EE + (fe < EE ? fe : EE - 1)];
            st[k] = ss[k]; snb[k] = nbr; sval[k] = vl; c += vl;
        }
        scnt = c; g_cnt[b] = c;
    }
    __syncthreads();
    float invc = 1.f / fmaxf((float)scnt, 1.f);
    for (int j = t; j < HH; j += 256) {
        float s = 0.f;
        for (int k = 0; k < 3; k++)
            if (sval[k])
                s += (X[(size_t)st[k]*HH + j] + X[(size_t)snb[k]*HH + j]) * 0.5f;
        g_meanpaths[b*HH + j] = s * invc;
    }
}

// ---------------- path select (agg vs batch-mean fallback) ----------------
__global__ void k_select() {
    int i = blockIdx.x * 256 + threadIdx.x;   // 32*768
    int b = i / HH;
    g_pathpre[i] = (g_cnt[b] > 0) ? g_agg[i] : g_bmean[i];
}

// ---------------- comb = [query, graph, path] ----------------
__global__ void k_comb(const float* __restrict__ query) {
    int i = blockIdx.x * 256 + threadIdx.x;   // 32*2304
    int b = i / (3*HH), j = i % (3*HH);
    float v;
    if (j < HH)        v = query[b*HH + j];
    else if (j < 2*HH) v = g_graph[b*HH + j - HH];
    else               v = g_path[b*HH + j - 2*HH];
    g_comb[i] = v;
}

// ---------------- layernorm (optional elementwise in2 multiply) ----------------
__global__ void k_ln(const float* __restrict__ in, const float* __restrict__ in2,
                     const float* __restrict__ gg, const float* __restrict__ bb,
                     float* __restrict__ out)
{
    int b = blockIdx.x, t = threadIdx.x;
    __shared__ float sx[HH];
    __shared__ float red[256];
    float s = 0.f;
    for (int j = t; j < HH; j += 256) {
        float v = in[b*HH + j];
        if (in2) v *= in2[b*HH + j];
        sx[j] = v; s += v;
    }
    red[t] = s; __syncthreads();
    for (int o = 128; o > 0; o >>= 1) { if (t < o) red[t] += red[t+o]; __syncthreads(); }
    float m = red[0] * (1.f / HH); __syncthreads();
    float vs = 0.f;
    for (int j = t; j < HH; j += 256) { float d = sx[j] - m; vs += d*d; }
    red[t] = vs; __syncthreads();
    for (int o = 128; o > 0; o >>= 1) { if (t < o) red[t] += red[t+o]; __syncthreads(); }
    float inv = rsqrtf(red[0] * (1.f / HH) + 1e-5f);
    for (int j = t; j < HH; j += 256)
        out[b*HH + j] = (sx[j] - m) * inv * gg[j] + bb[j];
}

// ---------------- host ----------------
static float* addrf(const void* sym) {
    void* p = nullptr;
    cudaGetSymbolAddress(&p, sym);
    return (float*)p;
}

extern "C" void kernel_launch(void* const* d_in, const int* in_sizes, int n_in,
                              void* d_out, int out_size)
{
    const float* query   = (const float*)d_in[0];
    const float* X       = (const float*)d_in[1];
    const int*   ei      = (const int*)  d_in[2];
    const int*   bidx    = (const int*)  d_in[3];
    const float* gr_wq   = (const float*)d_in[4];
    const float* gr_bq   = (const float*)d_in[5];
    const float* gr_aq_w = (const float*)d_in[6];
    const float* gr_aq_b = (const float*)d_in[7];
    const float* gr_ak_w = (const float*)d_in[8];
    // d_in[9] = gr_ak_b: constant per (b,h) score shift -> cancels in softmax
    const float* gr_av_w = (const float*)d_in[10];
    const float* gr_av_b = (const float*)d_in[11];
    const float* gr_ao_w = (const float*)d_in[12];
    const float* gr_ao_b = (const float*)d_in[13];
    const float* gr_ln_g = (const float*)d_in[14];
    const float* gr_ln_b = (const float*)d_in[15];
    const float* pf_wq   = (const float*)d_in[16];
    const float* pf_bq   = (const float*)d_in[17];
    const float* pf_wn   = (const float*)d_in[18];
    const float* pf_bn   = (const float*)d_in[19];
    const float* pf_a1_w = (const float*)d_in[20];
    const float* pf_a1_b = (const float*)d_in[21];
    const float* pf_a2_w = (const float*)d_in[22];
    const float* pf_a2_b = (const float*)d_in[23];
    const float* pf_ln_g = (const float*)d_in[24];
    const float* pf_ln_b = (const float*)d_in[25];
    const float* fu_gw   = (const float*)d_in[26];
    const float* fu_gb   = (const float*)d_in[27];
    const float* fu_pw   = (const float*)d_in[28];
    const float* fu_pb   = (const float*)d_in[29];
    const float* fu_ln_g = (const float*)d_in[30];
    const float* fu_ln_b = (const float*)d_in[31];
    float* out = (float*)d_out;

    float* p_qp     = addrf(g_qp);
    float* p_q      = addrf(g_q);
    float* p_qp2    = addrf(g_qp2);
    float* p_T      = addrf(g_T);
    float* p_U      = addrf(g_U);
    float* p_wsum   = addrf(g_wsum);
    float* p_meanx  = addrf(g_meanx);
    float* p_ctx    = addrf(g_ctx);
    float* p_tmp1   = addrf(g_tmp1);
    float* p_graph  = addrf(g_graph);
    float* p_meanp  = addrf(g_meanpaths);
    float* p_bmean  = addrf(g_bmean);
    float* p_agg1   = addrf(g_agg1);
    float* p_agg    = addrf(g_agg);
    float* p_ppre   = addrf(g_pathpre);
    float* p_path   = addrf(g_path);
    float* p_comb   = addrf(g_comb);
    float* p_gate   = addrf(g_gate);
    float* p_fused  = addrf(g_fused);

    k_init<<<NN/256, 256>>>();

    // --- tiny projections ---
    k_gemm<<<6, 256>>>(query, HH, gr_wq,   HH, 0, gr_bq,   p_qp,  HH, BB, HH, HH, 0);
    k_gemm<<<6, 256>>>(p_qp,  HH, gr_aq_w, HH, 0, gr_aq_b, p_q,   HH, BB, HH, HH, 0);
    k_gemm<<<6, 256>>>(query, HH, pf_wq,   HH, 0, pf_bq,   p_qp2, HH, BB, HH, HH, 0);
    k_qstats<<<BB, 256>>>(pf_bn);
    // T[b,:] = qp2_b @ Wn^T  (cosine numerator vector)
    k_gemm<<<6, 256>>>(p_qp2, HH, pf_wn, HH, 1, nullptr, p_T, HH, BB, HH, HH, 0);
    // U[b,h,:] = q[b,h-slice] @ (Wk head slice)^T  (score vectors, K GEMM eliminated)
    for (int h = 0; h < NH; h++)
        k_gemm<<<6, 256>>>(p_q + h*DHH, HH, gr_ak_w + h*DHH, HH, 1, nullptr,
                           p_U + h*HH, NH*HH, BB, HH, DHH, 0);

    // --- heavy passes over node_features ---
    k_scores<<<256, 256>>>(X);
    k_normgemm<<<dim3(NN/128, HH/128), 256>>>(X, pf_wn, pf_bn);

    // --- attention ---
    k_smstats<<<BB*NH, 256>>>();
    k_wsum<<<dim3(BB, HH/128), 128>>>(X);
    for (int h = 0; h < NH; h++)   // ctx head-slice = wsum[b,h,:] @ Wv slice + bv (V GEMM eliminated)
        k_gemm<<<1, 256>>>(p_wsum + h*HH, NH*HH, gr_av_w + h*DHH, HH, 0, gr_av_b + h*DHH,
                           p_ctx + h*DHH, HH, BB, DHH, HH, 0);
    k_gemm<<<6, 256>>>(p_ctx, HH, gr_ao_w, HH, 0, gr_ao_b, p_tmp1, HH, BB, HH, HH, 0);
    k_ln<<<BB, 256>>>(p_tmp1, nullptr, gr_ln_g, gr_ln_b, p_graph);

    // --- paths ---
    k_edges<<<EE/256, 256>>>(ei, bidx);
    k_paths<<<BB, 256>>>(X, ei);
    k_gemm<<<6, 256>>>(p_meanx, HH, pf_wn,   HH, 0, pf_bn,   p_bmean, HH, BB, HH, HH, 0);
    k_gemm<<<6, 256>>>(p_meanp, HH, pf_a1_w, HH, 0, pf_a1_b, p_agg1,  HH, BB, HH, HH, 1);
    k_gemm<<<6, 256>>>(p_agg1,  HH, pf_a2_w, HH, 0, pf_a2_b, p_agg,   HH, BB, HH, HH, 0);
    k_select<<<BB*HH/256, 256>>>();
    k_ln<<<BB, 256>>>(p_ppre, nullptr, pf_ln_g, pf_ln_b, p_path);

    // --- fusion ---
    k_comb<<<BB*3*HH/256, 256>>>(query);
    k_gemm<<<6, 256>>>(p_comb, 3*HH, fu_gw, HH, 0, fu_gb, p_gate,  HH, BB, HH, 3*HH, 2);
    k_gemm<<<6, 256>>>(p_comb, 3*HH, fu_pw, HH, 0, fu_pb, p_fused, HH, BB, HH, 3*HH, 0);
    k_ln<<<BB, 256>>>(p_fused, p_gate, fu_ln_g, fu_ln_b, out);
}